// round 8
// baseline (speedup 1.0000x reference)
#include <cuda_runtime.h>
#include <cuda_bf16.h>
#include <cstdint>

#define BATCH 4
#define SEQ   4096
#define DIN   256
#define DOUT  64
#define ROWS  (BATCH*SEQ)
#define BM    128
#define BN    128
#define NT    (SEQ/BN)

typedef uint32_t u32;
typedef unsigned short u16;
typedef unsigned long long ull;

// ---------------- attn smem layout (bytes, dynamic) ----------------
#define SQH 0
#define SQL 16384
#define SK  32768            // + buf*32768 ; lo at +16384
#define SV  98304            // + buf*32768 ; lo at +16384
#define ATTN_SMEM 163840

// ---------------- proj smem layout (bytes, dynamic) ----------------
#define PXH 0                // 4 chunk tiles [128][64] bf16, 16KB each
#define PXL 65536
#define PWH 131072           // [256 k][64 n] bf16, 128B rows
#define PWL 163840
#define PROJ_SMEM 196608

// ---------------- PTX helpers ----------------
__device__ __forceinline__ u32 smem_u32(const void* p) {
    u32 a;
    asm("{ .reg .u64 t; cvta.to.shared.u64 t, %1; cvt.u32.u64 %0, t; }"
        : "=r"(a) : "l"(p));
    return a;
}
#define CP16(dst, src) \
    asm volatile("cp.async.cg.shared.global [%0], [%1], 16;" \
                 :: "r"(dst), "l"(src) : "memory")
#define CPCOMMIT() asm volatile("cp.async.commit_group;" ::: "memory")
#define CPWAIT(n)  asm volatile("cp.async.wait_group %0;" :: "n"(n) : "memory")

#define LDSM4(r, a) \
    asm volatile("ldmatrix.sync.aligned.m8n8.x4.shared.b16 {%0,%1,%2,%3}, [%4];" \
                 : "=r"((r)[0]), "=r"((r)[1]), "=r"((r)[2]), "=r"((r)[3]) : "r"(a))
#define LDSM4T(r, a) \
    asm volatile("ldmatrix.sync.aligned.m8n8.x4.trans.shared.b16 {%0,%1,%2,%3}, [%4];" \
                 : "=r"((r)[0]), "=r"((r)[1]), "=r"((r)[2]), "=r"((r)[3]) : "r"(a))

__device__ __forceinline__ void mma16816(float* d, const u32* a, u32 b0, u32 b1) {
    asm volatile(
        "mma.sync.aligned.m16n8k16.row.col.f32.bf16.bf16.f32 "
        "{%0,%1,%2,%3},{%4,%5,%6,%7},{%8,%9},{%0,%1,%2,%3};"
        : "+f"(d[0]), "+f"(d[1]), "+f"(d[2]), "+f"(d[3])
        : "r"(a[0]), "r"(a[1]), "r"(a[2]), "r"(a[3]), "r"(b0), "r"(b1));
}

// bf16 split helpers
__device__ __forceinline__ u32 cvt2_bf16(float lo, float hi) {
    u32 r;
    asm("{ .reg .b16 a,b; cvt.rn.bf16.f32 a, %1; cvt.rn.bf16.f32 b, %2; mov.b32 %0, {a,b}; }"
        : "=r"(r) : "f"(lo), "f"(hi));
    return r;
}
__device__ __forceinline__ float bf16lo_f(u32 p) { return __uint_as_float(p << 16); }
__device__ __forceinline__ float bf16hi_f(u32 p) { return __uint_as_float(p & 0xffff0000u); }

// ---------------- device scratch: split-bf16 tensors ----------------
__device__ __nv_bfloat16 g_Qh[ROWS * DOUT];
__device__ __nv_bfloat16 g_Ql[ROWS * DOUT];
__device__ __nv_bfloat16 g_Kh[ROWS * DOUT];
__device__ __nv_bfloat16 g_Kl[ROWS * DOUT];
__device__ __nv_bfloat16 g_Vh[ROWS * DOUT];
__device__ __nv_bfloat16 g_Vl[ROWS * DOUT];

// =====================================================================
// Kernel 1: tensor-core QKV projection (3-term split-bf16)
// =====================================================================
__global__ void __launch_bounds__(256) qkv_proj_kernel(
    const float* __restrict__ x,
    const float* __restrict__ Wq, const float* __restrict__ bq,
    const float* __restrict__ Wk, const float* __restrict__ bk,
    const float* __restrict__ Wv, const float* __restrict__ bv)
{
    extern __shared__ char smc[];
    const u32 sb = smem_u32(smc);
    const int t = threadIdx.x;
    const int w = t >> 5, lane = t & 31;
    const int mt = lane >> 3, lr = lane & 7;
    const int m0 = blockIdx.x * 128;

    // ---- phase 1: load x [128][256] fp32, convert to split-bf16 tiles ----
    #pragma unroll
    for (int p = 0; p < 16; ++p) {
        int idx = t + p * 256;
        int row = idx >> 5, seg = idx & 31;
        const float4* src = (const float4*)(x + (size_t)(m0 + row) * DIN + seg * 8);
        float4 f0 = src[0], f1 = src[1];
        u32 h0 = cvt2_bf16(f0.x, f0.y), h1 = cvt2_bf16(f0.z, f0.w);
        u32 h2 = cvt2_bf16(f1.x, f1.y), h3 = cvt2_bf16(f1.z, f1.w);
        u32 g0 = cvt2_bf16(f0.x - bf16lo_f(h0), f0.y - bf16hi_f(h0));
        u32 g1 = cvt2_bf16(f0.z - bf16lo_f(h1), f0.w - bf16hi_f(h1));
        u32 g2 = cvt2_bf16(f1.x - bf16lo_f(h2), f1.y - bf16hi_f(h2));
        u32 g3 = cvt2_bf16(f1.z - bf16lo_f(h3), f1.w - bf16hi_f(h3));
        int chunk = seg >> 3, s7 = seg & 7;
        u32 off = chunk * 16384 + row * 128 + ((s7 ^ (row & 7)) * 16);
        asm volatile("st.shared.v4.b32 [%0], {%1,%2,%3,%4};"
                     :: "r"(sb + PXH + off), "r"(h0), "r"(h1), "r"(h2), "r"(h3) : "memory");
        asm volatile("st.shared.v4.b32 [%0], {%1,%2,%3,%4};"
                     :: "r"(sb + PXL + off), "r"(g0), "r"(g1), "r"(g2), "r"(g3) : "memory");
    }

    // ---- phase 2: per output, load W, MMA, epilogue ----
    for (int o = 0; o < 3; ++o) {
        const float* W    = (o == 0) ? Wq : (o == 1) ? Wk : Wv;
        const float* bias = (o == 0) ? bq : (o == 1) ? bk : bv;
        const float osc   = (o == 0) ? 0.125f : 1.0f;
        __nv_bfloat16* H  = (o == 0) ? g_Qh : (o == 1) ? g_Kh : g_Vh;
        __nv_bfloat16* L  = (o == 0) ? g_Ql : (o == 1) ? g_Kl : g_Vl;

        __syncthreads();   // prev-o ldsm reads done before W overwrite
        #pragma unroll
        for (int p = 0; p < 8; ++p) {
            int idx = t + p * 256;
            int row = idx >> 3, seg = idx & 7;
            const float4* src = (const float4*)(W + (size_t)row * 64 + seg * 8);
            float4 f0 = src[0], f1 = src[1];
            u32 h0 = cvt2_bf16(f0.x, f0.y), h1 = cvt2_bf16(f0.z, f0.w);
            u32 h2 = cvt2_bf16(f1.x, f1.y), h3 = cvt2_bf16(f1.z, f1.w);
            u32 g0 = cvt2_bf16(f0.x - bf16lo_f(h0), f0.y - bf16hi_f(h0));
            u32 g1 = cvt2_bf16(f0.z - bf16lo_f(h1), f0.w - bf16hi_f(h1));
            u32 g2 = cvt2_bf16(f1.x - bf16lo_f(h2), f1.y - bf16hi_f(h2));
            u32 g3 = cvt2_bf16(f1.z - bf16lo_f(h3), f1.w - bf16hi_f(h3));
            u32 off = row * 128 + ((seg ^ (row & 7)) * 16);
            asm volatile("st.shared.v4.b32 [%0], {%1,%2,%3,%4};"
                         :: "r"(sb + PWH + off), "r"(h0), "r"(h1), "r"(h2), "r"(h3) : "memory");
            asm volatile("st.shared.v4.b32 [%0], {%1,%2,%3,%4};"
                         :: "r"(sb + PWL + off), "r"(g0), "r"(g1), "r"(g2), "r"(g3) : "memory");
        }
        __syncthreads();

        float C[8][4];
        #pragma unroll
        for (int j = 0; j < 8; ++j)
            #pragma unroll
            for (int c = 0; c < 4; ++c) C[j][c] = 0.f;

        #pragma unroll 4
        for (int s = 0; s < 16; ++s) {            // k16 steps over DIN=256
            int arow = w * 16 + (mt & 1) * 8 + lr;
            int aseg = (s & 3) * 2 + (mt >> 1);
            u32 aoff = (u32)((s >> 2) * 16384 + arow * 128 + ((aseg ^ (arow & 7)) * 16));
            u32 ah[4], al[4];
            LDSM4(ah, sb + PXH + aoff);
            LDSM4(al, sb + PXL + aoff);
            int brow = s * 16 + (mt & 1) * 8 + lr;
            #pragma unroll
            for (int j = 0; j < 4; ++j) {          // n16 chunks
                int bseg = j * 2 + (mt >> 1);
                u32 boff = (u32)(brow * 128 + ((bseg ^ (brow & 7)) * 16));
                u32 bh[4], bl[4];
                LDSM4T(bh, sb + PWH + boff);
                LDSM4T(bl, sb + PWL + boff);
                mma16816(C[j * 2],     ah, bh[0], bh[1]);
                mma16816(C[j * 2],     ah, bl[0], bl[1]);
                mma16816(C[j * 2],     al, bh[0], bh[1]);
                mma16816(C[j * 2 + 1], ah, bh[2], bh[3]);
                mma16816(C[j * 2 + 1], ah, bl[2], bl[3]);
                mma16816(C[j * 2 + 1], al, bh[2], bh[3]);
            }
        }

        // epilogue: +bias, *osc, split, store
        const int r  = w * 16 + (lane >> 2);
        const int c0 = (lane & 3) * 2;
        u32* Hp = (u32*)H;
        u32* Lp = (u32*)L;
        #pragma unroll
        for (int j = 0; j < 8; ++j) {
            float b0 = bias[j * 8 + c0], b1 = bias[j * 8 + c0 + 1];
            float v0 = (C[j][0] + b0) * osc, v1 = (C[j][1] + b1) * osc;
            float v2 = (C[j][2] + b0) * osc, v3 = (C[j][3] + b1) * osc;
            u32 h01 = cvt2_bf16(v0, v1);
            u32 l01 = cvt2_bf16(v0 - bf16lo_f(h01), v1 - bf16hi_f(h01));
            u32 h23 = cvt2_bf16(v2, v3);
            u32 l23 = cvt2_bf16(v2 - bf16lo_f(h23), v3 - bf16hi_f(h23));
            size_t i0 = ((size_t)(m0 + r) * 64 + j * 8 + c0) >> 1;
            size_t i1 = ((size_t)(m0 + r + 8) * 64 + j * 8 + c0) >> 1;
            Hp[i0] = h01; Lp[i0] = l01;
            Hp[i1] = h23; Lp[i1] = l23;
        }
    }
}

// =====================================================================
// Kernel 2: mma.sync flash attention, cross-chunk software pipeline
// =====================================================================
__device__ __forceinline__ void load_tile(u32 sdst, const __nv_bfloat16* g, int t) {
    #pragma unroll
    for (int p = 0; p < 4; ++p) {
        int c = t + p * 256;
        int row = c >> 3, seg = c & 7;
        u32 dst = sdst + row * 128 + ((seg ^ (row & 7)) * 16);
        CP16(dst, g + row * 64 + seg * 8);
    }
}

// S chunk: 16 keys, 3-term split, accumulate into S[0..7]
__device__ __forceinline__ void comp_S(u32 kb, const u32 qh[4][4], const u32 ql[4][4],
                                       int c, int mt, int lr, float* S)
{
    #pragma unroll
    for (int j = 0; j < 8; ++j) S[j] = 0.f;
    #pragma unroll
    for (int ks = 0; ks < 4; ++ks) {
        int row = c * 16 + (mt >> 1) * 8 + lr;
        int seg = ks * 2 + (mt & 1);
        u32 soff = row * 128 + ((seg ^ (row & 7)) * 16);
        u32 bh[4], bl[4];
        LDSM4(bh, kb + soff);
        LDSM4(bl, kb + 16384 + soff);
        mma16816(S,     qh[ks], bh[0], bh[1]);
        mma16816(S,     qh[ks], bl[0], bl[1]);
        mma16816(S,     ql[ks], bh[0], bh[1]);
        mma16816(S + 4, qh[ks], bh[2], bh[3]);
        mma16816(S + 4, qh[ks], bl[2], bl[3]);
        mma16816(S + 4, ql[ks], bh[2], bh[3]);
    }
}

__global__ void __launch_bounds__(256, 1) attn_kernel(float* __restrict__ out)
{
    extern __shared__ char smc[];
    const u32 sbase = smem_u32(smc);

    const int t    = threadIdx.x;
    const int w    = t >> 5;
    const int lane = t & 31;
    const int mt   = lane >> 3, lr = lane & 7;
    const int b    = blockIdx.y;
    const int m0   = blockIdx.x * BM;

    const __nv_bfloat16* Khg = g_Kh + (size_t)b * SEQ * DOUT;
    const __nv_bfloat16* Klg = g_Kl + (size_t)b * SEQ * DOUT;
    const __nv_bfloat16* Vhg = g_Vh + (size_t)b * SEQ * DOUT;
    const __nv_bfloat16* Vlg = g_Vl + (size_t)b * SEQ * DOUT;

    // prologue: Q + tile0 (group 0), tile1 (group 1)
    load_tile(sbase + SQH, g_Qh + ((size_t)b * SEQ + m0) * DOUT, t);
    load_tile(sbase + SQL, g_Ql + ((size_t)b * SEQ + m0) * DOUT, t);
    load_tile(sbase + SK,          Khg, t);
    load_tile(sbase + SK + 16384,  Klg, t);
    load_tile(sbase + SV,          Vhg, t);
    load_tile(sbase + SV + 16384,  Vlg, t);
    CPCOMMIT();
    load_tile(sbase + SK + 32768,  Khg + BN * DOUT, t);
    load_tile(sbase + SK + 49152,  Klg + BN * DOUT, t);
    load_tile(sbase + SV + 32768,  Vhg + BN * DOUT, t);
    load_tile(sbase + SV + 49152,  Vlg + BN * DOUT, t);
    CPCOMMIT();

    CPWAIT(1);
    __syncthreads();

    // Q fragments (registers, whole kernel)
    u32 qh[4][4], ql[4][4];
    #pragma unroll
    for (int ks = 0; ks < 4; ++ks) {
        int row = w * 16 + (mt & 1) * 8 + lr;
        int seg = ks * 2 + (mt >> 1);
        u32 soff = row * 128 + ((seg ^ (row & 7)) * 16);
        LDSM4(qh[ks], sbase + SQH + soff);
        LDSM4(ql[ks], sbase + SQL + soff);
    }

    float Oacc[8][4];
    #pragma unroll
    for (int j = 0; j < 8; ++j)
        #pragma unroll
        for (int c = 0; c < 4; ++c) Oacc[j][c] = 0.f;
    float l0 = 0.f, l1 = 0.f;   // lane-local partial row sums

    for (int i = 0; i < NT; ++i) {
        if (i < NT - 2) { CPWAIT(1); } else { CPWAIT(0); }
        __syncthreads();

        const u32 kb = sbase + SK + (i & 1) * 32768;
        const u32 vb = sbase + SV + (i & 1) * 32768;

        float Sb[2][8];
        // prime the pipeline with S(chunk 0)
        comp_S(kb, qh, ql, w & 7, mt, lr, Sb[0]);

        #pragma unroll 2
        for (int cc = 0; cc < 8; ++cc) {
            const int cur = cc & 1;
            // issue S(c+1) first: independent tensor work covering exp/cvt below
            if (cc < 7)
                comp_S(kb, qh, ql, (cc + 1 + w) & 7, mt, lr, Sb[cur ^ 1]);

            const float* S = Sb[cur];
            // ---- exp + lane-local partial sums ----
            float e0 = __expf(S[0]), e1 = __expf(S[1]);
            float e2 = __expf(S[2]), e3 = __expf(S[3]);
            float f0 = __expf(S[4]), f1 = __expf(S[5]);
            float f2 = __expf(S[6]), f3 = __expf(S[7]);
            l0 += (e0 + e1) + (f0 + f1);
            l1 += (e2 + e3) + (f2 + f3);

            // ---- P fragment (C-layout == A-layout repack) ----
            u32 ah[4], al[4];
            ah[0] = cvt2_bf16(e0, e1);
            ah[1] = cvt2_bf16(e2, e3);
            ah[2] = cvt2_bf16(f0, f1);
            ah[3] = cvt2_bf16(f2, f3);
            al[0] = cvt2_bf16(e0 - bf16lo_f(ah[0]), e1 - bf16hi_f(ah[0]));
            al[1] = cvt2_bf16(e2 - bf16lo_f(ah[1]), e3 - bf16hi_f(ah[1]));
            al[2] = cvt2_bf16(f0 - bf16lo_f(ah[2]), f1 - bf16hi_f(ah[2]));
            al[3] = cvt2_bf16(f2 - bf16lo_f(ah[3]), f3 - bf16hi_f(ah[3]));

            // ---- PV chunk: O += P(16 keys) @ V ----
            const int c = (cc + w) & 7;
            #pragma unroll
            for (int nc = 0; nc < 4; ++nc) {
                int row = c * 16 + (mt & 1) * 8 + lr;
                int seg = nc * 2 + (mt >> 1);
                u32 soff = row * 128 + ((seg ^ (row & 7)) * 16);
                u32 vh4[4], vl4[4];
                LDSM4T(vh4, vb + soff);
                LDSM4T(vl4, vb + 16384 + soff);
                mma16816(Oacc[nc * 2],     ah, vh4[0], vh4[1]);
                mma16816(Oacc[nc * 2],     ah, vl4[0], vl4[1]);
                mma16816(Oacc[nc * 2],     al, vh4[0], vh4[1]);
                mma16816(Oacc[nc * 2 + 1], ah, vh4[2], vh4[3]);
                mma16816(Oacc[nc * 2 + 1], ah, vl4[2], vl4[3]);
                mma16816(Oacc[nc * 2 + 1], al, vh4[2], vh4[3]);
            }
        }

        __syncthreads();   // all warps done with buf (i&1)

        if (i + 2 < NT) {
            const int n2 = (i + 2) * BN;
            const u32 db = sbase + (i & 1) * 32768;
            load_tile(db + SK,         Khg + (size_t)n2 * DOUT, t);
            load_tile(db + SK + 16384, Klg + (size_t)n2 * DOUT, t);
            load_tile(db + SV,         Vhg + (size_t)n2 * DOUT, t);
            load_tile(db + SV + 16384, Vlg + (size_t)n2 * DOUT, t);
            CPCOMMIT();
        }
    }

    // ---- finalize: reduce lane partials over quad, divide, store ----
    l0 += __shfl_xor_sync(0xffffffffu, l0, 1);
    l0 += __shfl_xor_sync(0xffffffffu, l0, 2);
    l1 += __shfl_xor_sync(0xffffffffu, l1, 1);
    l1 += __shfl_xor_sync(0xffffffffu, l1, 2);
    const float inv0 = 1.0f / l0;
    const float inv1 = 1.0f / l1;
    const int r0 = m0 + w * 16 + (lane >> 2);
    const int c0 = (lane & 3) * 2;
    float* o0 = out + ((size_t)b * SEQ + r0) * DOUT;
    float* o1 = o0 + 8 * DOUT;
    #pragma unroll
    for (int j = 0; j < 8; ++j) {
        *(float2*)(o0 + j * 8 + c0) = make_float2(Oacc[j][0] * inv0, Oacc[j][1] * inv0);
        *(float2*)(o1 + j * 8 + c0) = make_float2(Oacc[j][2] * inv1, Oacc[j][3] * inv1);
    }
}

// =====================================================================
// Launch
// =====================================================================
extern "C" void kernel_launch(void* const* d_in, const int* in_sizes, int n_in,
                              void* d_out, int out_size)
{
    const float* x  = (const float*)d_in[0];
    const float* Wq = (const float*)d_in[1];
    const float* bq = (const float*)d_in[2];
    const float* Wk = (const float*)d_in[3];
    const float* bk = (const float*)d_in[4];
    const float* Wv = (const float*)d_in[5];
    const float* bv = (const float*)d_in[6];
    float* out = (float*)d_out;

    cudaFuncSetAttribute(qkv_proj_kernel, cudaFuncAttributeMaxDynamicSharedMemorySize,
                         PROJ_SMEM);
    cudaFuncSetAttribute(attn_kernel, cudaFuncAttributeMaxDynamicSharedMemorySize,
                         ATTN_SMEM);

    qkv_proj_kernel<<<ROWS / 128, 256, PROJ_SMEM>>>(x, Wq, bq, Wk, bk, Wv, bv);
    attn_kernel<<<dim3(SEQ / BM, BATCH), 256, ATTN_SMEM>>>(out);
}

// round 9
// speedup vs baseline: 1.2044x; 1.2044x over previous
#include <cuda_runtime.h>
#include <cuda_bf16.h>
#include <cstdint>

#define BATCH 4
#define SEQ   4096
#define DIN   256
#define DOUT  64
#define ROWS  (BATCH*SEQ)
#define BM    128
#define BN    128
#define NT    (SEQ/BN)

typedef uint32_t u32;
typedef unsigned short u16;
typedef unsigned long long ull;

// ---------------- attn smem layout (bytes, dynamic) ----------------
#define SQH 0
#define SQL 16384
#define SK  32768            // + buf*32768 ; lo at +16384
#define SV  98304            // + buf*32768 ; lo at +16384
#define ATTN_SMEM 163840

// ---------------- proj smem layout (bytes, dynamic) ----------------
#define PXH 0                // 4 chunk tiles [128][64] bf16, 16KB each
#define PXL 65536
#define PWH 131072           // [256 k][64 n] bf16, 128B rows
#define PWL 163840
#define PROJ_SMEM 196608

// ---------------- PTX helpers ----------------
__device__ __forceinline__ u32 smem_u32(const void* p) {
    u32 a;
    asm("{ .reg .u64 t; cvta.to.shared.u64 t, %1; cvt.u32.u64 %0, t; }"
        : "=r"(a) : "l"(p));
    return a;
}
#define CP16(dst, src) \
    asm volatile("cp.async.cg.shared.global [%0], [%1], 16;" \
                 :: "r"(dst), "l"(src) : "memory")
#define CPCOMMIT() asm volatile("cp.async.commit_group;" ::: "memory")
#define CPWAIT(n)  asm volatile("cp.async.wait_group %0;" :: "n"(n) : "memory")

#define LDSM4(r, a) \
    asm volatile("ldmatrix.sync.aligned.m8n8.x4.shared.b16 {%0,%1,%2,%3}, [%4];" \
                 : "=r"((r)[0]), "=r"((r)[1]), "=r"((r)[2]), "=r"((r)[3]) : "r"(a))
#define LDSM4T(r, a) \
    asm volatile("ldmatrix.sync.aligned.m8n8.x4.trans.shared.b16 {%0,%1,%2,%3}, [%4];" \
                 : "=r"((r)[0]), "=r"((r)[1]), "=r"((r)[2]), "=r"((r)[3]) : "r"(a))

__device__ __forceinline__ void mma16816(float* d, const u32* a, u32 b0, u32 b1) {
    asm volatile(
        "mma.sync.aligned.m16n8k16.row.col.f32.bf16.bf16.f32 "
        "{%0,%1,%2,%3},{%4,%5,%6,%7},{%8,%9},{%0,%1,%2,%3};"
        : "+f"(d[0]), "+f"(d[1]), "+f"(d[2]), "+f"(d[3])
        : "r"(a[0]), "r"(a[1]), "r"(a[2]), "r"(a[3]), "r"(b0), "r"(b1));
}

// bf16 split helpers
__device__ __forceinline__ u32 cvt2_bf16(float lo, float hi) {
    u32 r;
    asm("{ .reg .b16 a,b; cvt.rn.bf16.f32 a, %1; cvt.rn.bf16.f32 b, %2; mov.b32 %0, {a,b}; }"
        : "=r"(r) : "f"(lo), "f"(hi));
    return r;
}
__device__ __forceinline__ float bf16lo_f(u32 p) { return __uint_as_float(p << 16); }
__device__ __forceinline__ float bf16hi_f(u32 p) { return __uint_as_float(p & 0xffff0000u); }

// ---------------- device scratch: split-bf16 tensors ----------------
__device__ __nv_bfloat16 g_Qh[ROWS * DOUT];
__device__ __nv_bfloat16 g_Ql[ROWS * DOUT];
__device__ __nv_bfloat16 g_Kh[ROWS * DOUT];
__device__ __nv_bfloat16 g_Kl[ROWS * DOUT];
__device__ __nv_bfloat16 g_Vh[ROWS * DOUT];
__device__ __nv_bfloat16 g_Vl[ROWS * DOUT];

// =====================================================================
// Kernel 1: tensor-core QKV projection (3-term split-bf16)
// =====================================================================
__global__ void __launch_bounds__(256) qkv_proj_kernel(
    const float* __restrict__ x,
    const float* __restrict__ Wq, const float* __restrict__ bq,
    const float* __restrict__ Wk, const float* __restrict__ bk,
    const float* __restrict__ Wv, const float* __restrict__ bv)
{
    extern __shared__ char smc[];
    const u32 sb = smem_u32(smc);
    const int t = threadIdx.x;
    const int w = t >> 5, lane = t & 31;
    const int mt = lane >> 3, lr = lane & 7;
    const int m0 = blockIdx.x * 128;

    // ---- phase 1: load x [128][256] fp32, convert to split-bf16 tiles ----
    #pragma unroll
    for (int p = 0; p < 16; ++p) {
        int idx = t + p * 256;
        int row = idx >> 5, seg = idx & 31;
        const float4* src = (const float4*)(x + (size_t)(m0 + row) * DIN + seg * 8);
        float4 f0 = src[0], f1 = src[1];
        u32 h0 = cvt2_bf16(f0.x, f0.y), h1 = cvt2_bf16(f0.z, f0.w);
        u32 h2 = cvt2_bf16(f1.x, f1.y), h3 = cvt2_bf16(f1.z, f1.w);
        u32 g0 = cvt2_bf16(f0.x - bf16lo_f(h0), f0.y - bf16hi_f(h0));
        u32 g1 = cvt2_bf16(f0.z - bf16lo_f(h1), f0.w - bf16hi_f(h1));
        u32 g2 = cvt2_bf16(f1.x - bf16lo_f(h2), f1.y - bf16hi_f(h2));
        u32 g3 = cvt2_bf16(f1.z - bf16lo_f(h3), f1.w - bf16hi_f(h3));
        int chunk = seg >> 3, s7 = seg & 7;
        u32 off = chunk * 16384 + row * 128 + ((s7 ^ (row & 7)) * 16);
        asm volatile("st.shared.v4.b32 [%0], {%1,%2,%3,%4};"
                     :: "r"(sb + PXH + off), "r"(h0), "r"(h1), "r"(h2), "r"(h3) : "memory");
        asm volatile("st.shared.v4.b32 [%0], {%1,%2,%3,%4};"
                     :: "r"(sb + PXL + off), "r"(g0), "r"(g1), "r"(g2), "r"(g3) : "memory");
    }

    // ---- phase 2: per output, load W, MMA, epilogue ----
    for (int o = 0; o < 3; ++o) {
        const float* W    = (o == 0) ? Wq : (o == 1) ? Wk : Wv;
        const float* bias = (o == 0) ? bq : (o == 1) ? bk : bv;
        const float osc   = (o == 0) ? 0.125f : 1.0f;
        __nv_bfloat16* H  = (o == 0) ? g_Qh : (o == 1) ? g_Kh : g_Vh;
        __nv_bfloat16* L  = (o == 0) ? g_Ql : (o == 1) ? g_Kl : g_Vl;

        __syncthreads();   // prev-o ldsm reads done before W overwrite
        #pragma unroll
        for (int p = 0; p < 8; ++p) {
            int idx = t + p * 256;
            int row = idx >> 3, seg = idx & 7;
            const float4* src = (const float4*)(W + (size_t)row * 64 + seg * 8);
            float4 f0 = src[0], f1 = src[1];
            u32 h0 = cvt2_bf16(f0.x, f0.y), h1 = cvt2_bf16(f0.z, f0.w);
            u32 h2 = cvt2_bf16(f1.x, f1.y), h3 = cvt2_bf16(f1.z, f1.w);
            u32 g0 = cvt2_bf16(f0.x - bf16lo_f(h0), f0.y - bf16hi_f(h0));
            u32 g1 = cvt2_bf16(f0.z - bf16lo_f(h1), f0.w - bf16hi_f(h1));
            u32 g2 = cvt2_bf16(f1.x - bf16lo_f(h2), f1.y - bf16hi_f(h2));
            u32 g3 = cvt2_bf16(f1.z - bf16lo_f(h3), f1.w - bf16hi_f(h3));
            u32 off = row * 128 + ((seg ^ (row & 7)) * 16);
            asm volatile("st.shared.v4.b32 [%0], {%1,%2,%3,%4};"
                         :: "r"(sb + PWH + off), "r"(h0), "r"(h1), "r"(h2), "r"(h3) : "memory");
            asm volatile("st.shared.v4.b32 [%0], {%1,%2,%3,%4};"
                         :: "r"(sb + PWL + off), "r"(g0), "r"(g1), "r"(g2), "r"(g3) : "memory");
        }
        __syncthreads();

        float C[8][4];
        #pragma unroll
        for (int j = 0; j < 8; ++j)
            #pragma unroll
            for (int c = 0; c < 4; ++c) C[j][c] = 0.f;

        #pragma unroll 4
        for (int s = 0; s < 16; ++s) {            // k16 steps over DIN=256
            int arow = w * 16 + (mt & 1) * 8 + lr;
            int aseg = (s & 3) * 2 + (mt >> 1);
            u32 aoff = (u32)((s >> 2) * 16384 + arow * 128 + ((aseg ^ (arow & 7)) * 16));
            u32 ah[4], al[4];
            LDSM4(ah, sb + PXH + aoff);
            LDSM4(al, sb + PXL + aoff);
            int brow = s * 16 + (mt & 1) * 8 + lr;
            #pragma unroll
            for (int j = 0; j < 4; ++j) {          // n16 chunks
                int bseg = j * 2 + (mt >> 1);
                u32 boff = (u32)(brow * 128 + ((bseg ^ (brow & 7)) * 16));
                u32 bh[4], bl[4];
                LDSM4T(bh, sb + PWH + boff);
                LDSM4T(bl, sb + PWL + boff);
                mma16816(C[j * 2],     ah, bh[0], bh[1]);
                mma16816(C[j * 2],     ah, bl[0], bl[1]);
                mma16816(C[j * 2],     al, bh[0], bh[1]);
                mma16816(C[j * 2 + 1], ah, bh[2], bh[3]);
                mma16816(C[j * 2 + 1], ah, bl[2], bl[3]);
                mma16816(C[j * 2 + 1], al, bh[2], bh[3]);
            }
        }

        // epilogue: +bias, *osc, split, store
        const int r  = w * 16 + (lane >> 2);
        const int c0 = (lane & 3) * 2;
        u32* Hp = (u32*)H;
        u32* Lp = (u32*)L;
        #pragma unroll
        for (int j = 0; j < 8; ++j) {
            float b0 = bias[j * 8 + c0], b1 = bias[j * 8 + c0 + 1];
            float v0 = (C[j][0] + b0) * osc, v1 = (C[j][1] + b1) * osc;
            float v2 = (C[j][2] + b0) * osc, v3 = (C[j][3] + b1) * osc;
            u32 h01 = cvt2_bf16(v0, v1);
            u32 l01 = cvt2_bf16(v0 - bf16lo_f(h01), v1 - bf16hi_f(h01));
            u32 h23 = cvt2_bf16(v2, v3);
            u32 l23 = cvt2_bf16(v2 - bf16lo_f(h23), v3 - bf16hi_f(h23));
            size_t i0 = ((size_t)(m0 + r) * 64 + j * 8 + c0) >> 1;
            size_t i1 = ((size_t)(m0 + r + 8) * 64 + j * 8 + c0) >> 1;
            Hp[i0] = h01; Lp[i0] = l01;
            Hp[i1] = h23; Lp[i1] = l23;
        }
    }
}

// =====================================================================
// Kernel 2: mma.sync flash attention, chunked (R6 schedule),
//           3-term S / 2-term PV (O = sum Ph * (Vh + Vl))
// =====================================================================
__device__ __forceinline__ void load_tile(u32 sdst, const __nv_bfloat16* g, int t) {
    #pragma unroll
    for (int p = 0; p < 4; ++p) {
        int c = t + p * 256;
        int row = c >> 3, seg = c & 7;
        u32 dst = sdst + row * 128 + ((seg ^ (row & 7)) * 16);
        CP16(dst, g + row * 64 + seg * 8);
    }
}

__global__ void __launch_bounds__(256, 1) attn_kernel(float* __restrict__ out)
{
    extern __shared__ char smc[];
    const u32 sbase = smem_u32(smc);

    const int t    = threadIdx.x;
    const int w    = t >> 5;
    const int lane = t & 31;
    const int mt   = lane >> 3, lr = lane & 7;
    const int b    = blockIdx.y;
    const int m0   = blockIdx.x * BM;

    const __nv_bfloat16* Khg = g_Kh + (size_t)b * SEQ * DOUT;
    const __nv_bfloat16* Klg = g_Kl + (size_t)b * SEQ * DOUT;
    const __nv_bfloat16* Vhg = g_Vh + (size_t)b * SEQ * DOUT;
    const __nv_bfloat16* Vlg = g_Vl + (size_t)b * SEQ * DOUT;

    // prologue: Q + tile0 (group 0), tile1 (group 1)
    load_tile(sbase + SQH, g_Qh + ((size_t)b * SEQ + m0) * DOUT, t);
    load_tile(sbase + SQL, g_Ql + ((size_t)b * SEQ + m0) * DOUT, t);
    load_tile(sbase + SK,          Khg, t);
    load_tile(sbase + SK + 16384,  Klg, t);
    load_tile(sbase + SV,          Vhg, t);
    load_tile(sbase + SV + 16384,  Vlg, t);
    CPCOMMIT();
    load_tile(sbase + SK + 32768,  Khg + BN * DOUT, t);
    load_tile(sbase + SK + 49152,  Klg + BN * DOUT, t);
    load_tile(sbase + SV + 32768,  Vhg + BN * DOUT, t);
    load_tile(sbase + SV + 49152,  Vlg + BN * DOUT, t);
    CPCOMMIT();

    CPWAIT(1);
    __syncthreads();

    // Q fragments (registers, whole kernel)
    u32 qh[4][4], ql[4][4];
    #pragma unroll
    for (int ks = 0; ks < 4; ++ks) {
        int row = w * 16 + (mt & 1) * 8 + lr;
        int seg = ks * 2 + (mt >> 1);
        u32 soff = row * 128 + ((seg ^ (row & 7)) * 16);
        LDSM4(qh[ks], sbase + SQH + soff);
        LDSM4(ql[ks], sbase + SQL + soff);
    }

    float Oacc[8][4];
    #pragma unroll
    for (int j = 0; j < 8; ++j)
        #pragma unroll
        for (int c = 0; c < 4; ++c) Oacc[j][c] = 0.f;
    float l0 = 0.f, l1 = 0.f;   // lane-local partial row sums

    for (int i = 0; i < NT; ++i) {
        if (i < NT - 2) { CPWAIT(1); } else { CPWAIT(0); }
        __syncthreads();

        const u32 kb = sbase + SK + (i & 1) * 32768;
        const u32 vb = sbase + SV + (i & 1) * 32768;

        #pragma unroll 2
        for (int cc = 0; cc < 8; ++cc) {
            const int c = (cc + w) & 7;            // warp-rotated chunk order

            // ---- S chunk: 16 keys, 3-term split ----
            float S0[4] = {0.f, 0.f, 0.f, 0.f};
            float S1[4] = {0.f, 0.f, 0.f, 0.f};
            #pragma unroll
            for (int ks = 0; ks < 4; ++ks) {
                int row = c * 16 + (mt >> 1) * 8 + lr;
                int seg = ks * 2 + (mt & 1);
                u32 soff = row * 128 + ((seg ^ (row & 7)) * 16);
                u32 bh[4], bl[4];
                LDSM4(bh, kb + soff);
                LDSM4(bl, kb + 16384 + soff);
                mma16816(S0, qh[ks], bh[0], bh[1]);
                mma16816(S0, qh[ks], bl[0], bl[1]);
                mma16816(S0, ql[ks], bh[0], bh[1]);
                mma16816(S1, qh[ks], bh[2], bh[3]);
                mma16816(S1, qh[ks], bl[2], bl[3]);
                mma16816(S1, ql[ks], bh[2], bh[3]);
            }

            // ---- exp + lane-local partial sums ----
            float e0 = __expf(S0[0]), e1 = __expf(S0[1]);
            float e2 = __expf(S0[2]), e3 = __expf(S0[3]);
            float f0 = __expf(S1[0]), f1 = __expf(S1[1]);
            float f2 = __expf(S1[2]), f3 = __expf(S1[3]);
            l0 += (e0 + e1) + (f0 + f1);
            l1 += (e2 + e3) + (f2 + f3);

            // ---- P fragment, hi only (C-layout == A-layout repack) ----
            u32 ah[4];
            ah[0] = cvt2_bf16(e0, e1);
            ah[1] = cvt2_bf16(e2, e3);
            ah[2] = cvt2_bf16(f0, f1);
            ah[3] = cvt2_bf16(f2, f3);

            // ---- PV chunk: O += Ph @ (Vh + Vl), 2-term ----
            #pragma unroll
            for (int nc = 0; nc < 4; ++nc) {
                int row = c * 16 + (mt & 1) * 8 + lr;
                int seg = nc * 2 + (mt >> 1);
                u32 soff = row * 128 + ((seg ^ (row & 7)) * 16);
                u32 vh4[4], vl4[4];
                LDSM4T(vh4, vb + soff);
                LDSM4T(vl4, vb + 16384 + soff);
                mma16816(Oacc[nc * 2],     ah, vh4[0], vh4[1]);
                mma16816(Oacc[nc * 2],     ah, vl4[0], vl4[1]);
                mma16816(Oacc[nc * 2 + 1], ah, vh4[2], vh4[3]);
                mma16816(Oacc[nc * 2 + 1], ah, vl4[2], vl4[3]);
            }
        }

        __syncthreads();   // all warps done with buf (i&1)

        if (i + 2 < NT) {
            const int n2 = (i + 2) * BN;
            const u32 db = sbase + (i & 1) * 32768;
            load_tile(db + SK,         Khg + (size_t)n2 * DOUT, t);
            load_tile(db + SK + 16384, Klg + (size_t)n2 * DOUT, t);
            load_tile(db + SV,         Vhg + (size_t)n2 * DOUT, t);
            load_tile(db + SV + 16384, Vlg + (size_t)n2 * DOUT, t);
            CPCOMMIT();
        }
    }

    // ---- finalize: reduce lane partials over quad, divide, store ----
    l0 += __shfl_xor_sync(0xffffffffu, l0, 1);
    l0 += __shfl_xor_sync(0xffffffffu, l0, 2);
    l1 += __shfl_xor_sync(0xffffffffu, l1, 1);
    l1 += __shfl_xor_sync(0xffffffffu, l1, 2);
    const float inv0 = 1.0f / l0;
    const float inv1 = 1.0f / l1;
    const int r0 = m0 + w * 16 + (lane >> 2);
    const int c0 = (lane & 3) * 2;
    float* o0 = out + ((size_t)b * SEQ + r0) * DOUT;
    float* o1 = o0 + 8 * DOUT;
    #pragma unroll
    for (int j = 0; j < 8; ++j) {
        *(float2*)(o0 + j * 8 + c0) = make_float2(Oacc[j][0] * inv0, Oacc[j][1] * inv0);
        *(float2*)(o1 + j * 8 + c0) = make_float2(Oacc[j][2] * inv1, Oacc[j][3] * inv1);
    }
}

// =====================================================================
// Launch
// =====================================================================
extern "C" void kernel_launch(void* const* d_in, const int* in_sizes, int n_in,
                              void* d_out, int out_size)
{
    const float* x  = (const float*)d_in[0];
    const float* Wq = (const float*)d_in[1];
    const float* bq = (const float*)d_in[2];
    const float* Wk = (const float*)d_in[3];
    const float* bk = (const float*)d_in[4];
    const float* Wv = (const float*)d_in[5];
    const float* bv = (const float*)d_in[6];
    float* out = (float*)d_out;

    cudaFuncSetAttribute(qkv_proj_kernel, cudaFuncAttributeMaxDynamicSharedMemorySize,
                         PROJ_SMEM);
    cudaFuncSetAttribute(attn_kernel, cudaFuncAttributeMaxDynamicSharedMemorySize,
                         ATTN_SMEM);

    qkv_proj_kernel<<<ROWS / 128, 256, PROJ_SMEM>>>(x, Wq, bq, Wk, bk, Wv, bv);
    attn_kernel<<<dim3(SEQ / BM, BATCH), 256, ATTN_SMEM>>>(out);
}